// round 1
// baseline (speedup 1.0000x reference)
#include <cuda_runtime.h>
#include <cstdint>
#include <cstddef>

#define B_ 2
#define L_ 4096
#define DM 2048
#define H_ 32
#define P_ 64
#define N_ 128
#define INTER 2048
#define CONV_DIM 2304
#define PROJ 4384
#define EPSV 1e-5f

// ---------------- scratch (no allocations allowed; __device__ globals) -----
__device__ float g_proj[(size_t)B_ * L_ * PROJ];      // 143.6 MB
__device__ float g_conv[(size_t)B_ * L_ * CONV_DIM];  // 75.5 MB
__device__ float g_y[(size_t)B_ * L_ * INTER];        // 67 MB
__device__ float g_dA[B_ * L_ * H_];
__device__ float g_dt[B_ * L_ * H_];

// ---------------- helpers ---------------------------------------------------
__device__ __forceinline__ float siluf(float x) {
    return x * (1.f / (1.f + expf(-x)));
}
__device__ __forceinline__ float softplusf(float x) {
    return (x > 20.f) ? x : log1pf(expf(x));
}
__device__ __forceinline__ uint32_t s2u(const void* p) {
    return (uint32_t)__cvta_generic_to_shared(p);
}
__device__ __forceinline__ void cp_async4(uint32_t saddr, const void* g) {
    asm volatile("cp.async.ca.shared.global [%0], [%1], 4;\n" :: "r"(saddr), "l"(g));
}
__device__ __forceinline__ void cp_commit() {
    asm volatile("cp.async.commit_group;\n" ::: "memory");
}
__device__ __forceinline__ void cp_wait2() {
    asm volatile("cp.async.wait_group 2;\n" ::: "memory");
}

// ---------------- SGEMM: C[m,n] = sum_k A[m,K]*Bt[n,K]  (both K-contiguous) -
__device__ __forceinline__ void stTile(float dst[16][128], int kq, int r, float4 v) {
    dst[kq + 0][r] = v.x; dst[kq + 1][r] = v.y; dst[kq + 2][r] = v.z; dst[kq + 3][r] = v.w;
}

template <int GUARDN>
__global__ __launch_bounds__(256, 2)
void sgemm_nt(const float* __restrict__ A, const float* __restrict__ Bt,
              float* __restrict__ C, int M, int N, int K)
{
    __shared__ float As[2][16][128];
    __shared__ float Bs[2][16][128];
    const int tid = threadIdx.x;
    const int bm = blockIdx.y * 128;
    const int bn = blockIdx.x * 128;
    const int tx = tid & 15;
    const int ty = tid >> 4;
    const int r0 = tid >> 2;         // 0..63
    const int r1 = r0 + 64;          // 64..127
    const int kq = (tid & 3) << 2;   // 0,4,8,12

    const float* Ag0 = A + (size_t)(bm + r0) * K + kq;
    const float* Ag1 = A + (size_t)(bm + r1) * K + kq;
    const float* Bg0 = Bt + (size_t)(bn + r0) * K + kq;
    const float* Bg1 = Bt + (size_t)(bn + r1) * K + kq;
    bool v0 = true, v1 = true;
    if (GUARDN) { v0 = (bn + r0) < N; v1 = (bn + r1) < N; }
    const float4 z4 = make_float4(0.f, 0.f, 0.f, 0.f);

    float4 ra0 = *(const float4*)Ag0;
    float4 ra1 = *(const float4*)Ag1;
    float4 rb0 = v0 ? *(const float4*)Bg0 : z4;
    float4 rb1 = v1 ? *(const float4*)Bg1 : z4;
    stTile(As[0], kq, r0, ra0); stTile(As[0], kq, r1, ra1);
    stTile(Bs[0], kq, r0, rb0); stTile(Bs[0], kq, r1, rb1);
    __syncthreads();

    float acc[8][8];
#pragma unroll
    for (int i = 0; i < 8; ++i)
#pragma unroll
        for (int j = 0; j < 8; ++j) acc[i][j] = 0.f;

    const int kTiles = K >> 4;
    for (int kt = 0; kt < kTiles; ++kt) {
        const int cur = kt & 1;
        if (kt + 1 < kTiles) {
            const size_t off = (size_t)(kt + 1) * 16;
            ra0 = *(const float4*)(Ag0 + off);
            ra1 = *(const float4*)(Ag1 + off);
            rb0 = v0 ? *(const float4*)(Bg0 + off) : z4;
            rb1 = v1 ? *(const float4*)(Bg1 + off) : z4;
        }
#pragma unroll
        for (int kk = 0; kk < 16; ++kk) {
            float af[8], bf[8];
            *(float4*)&af[0] = *(const float4*)&As[cur][kk][ty * 4];
            *(float4*)&af[4] = *(const float4*)&As[cur][kk][64 + ty * 4];
            *(float4*)&bf[0] = *(const float4*)&Bs[cur][kk][tx * 4];
            *(float4*)&bf[4] = *(const float4*)&Bs[cur][kk][64 + tx * 4];
#pragma unroll
            for (int i = 0; i < 8; ++i)
#pragma unroll
                for (int j = 0; j < 8; ++j)
                    acc[i][j] = fmaf(af[i], bf[j], acc[i][j]);
        }
        if (kt + 1 < kTiles) {
            const int nxt = cur ^ 1;
            stTile(As[nxt], kq, r0, ra0); stTile(As[nxt], kq, r1, ra1);
            stTile(Bs[nxt], kq, r0, rb0); stTile(Bs[nxt], kq, r1, rb1);
            __syncthreads();
        }
    }

#pragma unroll
    for (int i = 0; i < 8; ++i) {
        const int row = bm + ((i < 4) ? (ty * 4 + i) : (64 + ty * 4 + (i - 4)));
        float* Cr = C + (size_t)row * N;
        const int c0 = bn + tx * 4;
        const int c1 = bn + 64 + tx * 4;
        if (!GUARDN || c0 < N)
            *(float4*)(Cr + c0) = make_float4(acc[i][0], acc[i][1], acc[i][2], acc[i][3]);
        if (!GUARDN || c1 < N)
            *(float4*)(Cr + c1) = make_float4(acc[i][4], acc[i][5], acc[i][6], acc[i][7]);
    }
}

// ---------------- depthwise causal conv (K=4) + bias + SiLU ------------------
__global__ __launch_bounds__(256)
void conv_kernel(const float* __restrict__ conv_w, const float* __restrict__ conv_b)
{
    const int c = blockIdx.x * 256 + threadIdx.x;
    if (c >= CONV_DIM) return;
    const int bl = blockIdx.y;           // 0 .. B*L-1
    const int l = bl & (L_ - 1);
    float acc = conv_b[c];
    const float* w = conv_w + c * 4;
#pragma unroll
    for (int j = 0; j < 4; ++j) {
        const int ll = l - 3 + j;
        if (ll >= 0)
            acc = fmaf(g_proj[(size_t)(bl + j - 3) * PROJ + INTER + c], w[j], acc);
    }
    g_conv[(size_t)bl * CONV_DIM + c] = siluf(acc);
}

// ---------------- dt = softplus(dt_raw + bias); dA = exp(dt*A) ---------------
__global__ __launch_bounds__(256)
void dt_kernel(const float* __restrict__ dt_bias, const float* __restrict__ A_log)
{
    const int idx = blockIdx.x * 256 + threadIdx.x;   // B*L*H
    if (idx >= B_ * L_ * H_) return;
    const int hh = idx & (H_ - 1);
    const int bl = idx >> 5;
    const float x = g_proj[(size_t)bl * PROJ + INTER + CONV_DIM + hh] + dt_bias[hh];
    const float dt = softplusf(x);
    const float A = -expf(A_log[hh]);
    g_dt[idx] = dt;
    g_dA[idx] = expf(dt * A);
}

// ---------------- selective scan --------------------------------------------
// Block = (b, h, p-half). 256 threads: thread = (pg 0..15)*(ng 0..15).
// Thread owns p = ph*32 + pg*2 + {0,1}, n = {64*j + ng*4 + c : j<2, c<4}.
// 4-deep cp.async smem pipeline for per-timestep B/C/x/dA/dt.
__global__ __launch_bounds__(256)
void scan_kernel()
{
    const int blk = blockIdx.x;           // 0..127
    const int ph = blk & 1;
    const int h = (blk >> 1) & (H_ - 1);
    const int b = blk >> 6;
    const int tid = threadIdx.x;
    const int pg = tid >> 4;
    const int ng = tid & 15;

    __shared__ float sB[4][128];
    __shared__ float sC[4][128];
    __shared__ float sx[4][32];
    __shared__ float sS[4][2];

    auto issue = [&](int t, int s) {
        const float* base = g_conv + (size_t)(b * L_ + t) * CONV_DIM;
        if (tid < 128) cp_async4(s2u(&sB[s][tid]), base + INTER + tid);
        else           cp_async4(s2u(&sC[s][tid - 128]), base + INTER + N_ + (tid - 128));
        if (tid < 32)       cp_async4(s2u(&sx[s][tid]), base + h * P_ + ph * 32 + tid);
        else if (tid == 32) cp_async4(s2u(&sS[s][0]), g_dA + (b * L_ + t) * H_ + h);
        else if (tid == 33) cp_async4(s2u(&sS[s][1]), g_dt + (b * L_ + t) * H_ + h);
    };

    for (int t = 0; t < 3; ++t) { issue(t, t); cp_commit(); }

    float hst[16];
#pragma unroll
    for (int i = 0; i < 16; ++i) hst[i] = 0.f;

    for (int t = 0; t < L_; ++t) {
        cp_wait2();
        __syncthreads();
        if (t + 3 < L_) issue(t + 3, (t + 3) & 3);
        cp_commit();

        const int s = t & 3;
        const float dA = sS[s][0];
        const float dtv = sS[s][1];
        const float2 xp = *(const float2*)&sx[s][pg * 2];
        const float dtx0 = dtv * xp.x;
        const float dtx1 = dtv * xp.y;
        float acc0 = 0.f, acc1 = 0.f;
#pragma unroll
        for (int j = 0; j < 2; ++j) {
            const float4 b4 = *(const float4*)&sB[s][j * 64 + ng * 4];
            const float4 c4 = *(const float4*)&sC[s][j * 64 + ng * 4];
            float* h0 = &hst[j * 4];
            float* h1 = &hst[8 + j * 4];
            h0[0] = fmaf(dA, h0[0], dtx0 * b4.x); acc0 = fmaf(h0[0], c4.x, acc0);
            h0[1] = fmaf(dA, h0[1], dtx0 * b4.y); acc0 = fmaf(h0[1], c4.y, acc0);
            h0[2] = fmaf(dA, h0[2], dtx0 * b4.z); acc0 = fmaf(h0[2], c4.z, acc0);
            h0[3] = fmaf(dA, h0[3], dtx0 * b4.w); acc0 = fmaf(h0[3], c4.w, acc0);
            h1[0] = fmaf(dA, h1[0], dtx1 * b4.x); acc1 = fmaf(h1[0], c4.x, acc1);
            h1[1] = fmaf(dA, h1[1], dtx1 * b4.y); acc1 = fmaf(h1[1], c4.y, acc1);
            h1[2] = fmaf(dA, h1[2], dtx1 * b4.z); acc1 = fmaf(h1[2], c4.z, acc1);
            h1[3] = fmaf(dA, h1[3], dtx1 * b4.w); acc1 = fmaf(h1[3], c4.w, acc1);
        }
#pragma unroll
        for (int o = 8; o; o >>= 1) {
            acc0 += __shfl_xor_sync(0xffffffffu, acc0, o);
            acc1 += __shfl_xor_sync(0xffffffffu, acc1, o);
        }
        if (ng == 0) {
            *(float2*)&g_y[(size_t)(b * L_ + t) * INTER + h * P_ + ph * 32 + pg * 2] =
                make_float2(acc0, acc1);
        }
    }
}

// ---------------- y + D*xs, gate*silu, RMSNorm -------------------------------
__global__ __launch_bounds__(256)
void gate_rms_kernel(const float* __restrict__ D_param, const float* __restrict__ norm_w)
{
    const int bl = blockIdx.x;
    const int tid = threadIdx.x;
    float* yrow = g_y + (size_t)bl * INTER;
    const float* grow = g_proj + (size_t)bl * PROJ;
    const float* xrow = g_conv + (size_t)bl * CONV_DIM;

    float vals[8];
    float ss = 0.f;
#pragma unroll
    for (int r = 0; r < 2; ++r) {
        const int i = tid * 4 + r * 1024;
        const float4 yv = *(const float4*)(yrow + i);
        const float4 gv = *(const float4*)(grow + i);
        const float4 xv = *(const float4*)(xrow + i);
        const float d = D_param[i >> 6];
        float g0 = (yv.x + d * xv.x) * siluf(gv.x);
        float g1 = (yv.y + d * xv.y) * siluf(gv.y);
        float g2 = (yv.z + d * xv.z) * siluf(gv.z);
        float g3 = (yv.w + d * xv.w) * siluf(gv.w);
        vals[r * 4 + 0] = g0; vals[r * 4 + 1] = g1;
        vals[r * 4 + 2] = g2; vals[r * 4 + 3] = g3;
        ss += g0 * g0 + g1 * g1 + g2 * g2 + g3 * g3;
    }

    __shared__ float red[8];
    __shared__ float stot;
#pragma unroll
    for (int o = 16; o; o >>= 1) ss += __shfl_xor_sync(0xffffffffu, ss, o);
    if ((tid & 31) == 0) red[tid >> 5] = ss;
    __syncthreads();
    if (tid == 0) {
        float v = 0.f;
#pragma unroll
        for (int i = 0; i < 8; ++i) v += red[i];
        stot = rsqrtf(v * (1.f / (float)INTER) + EPSV);
    }
    __syncthreads();
    const float rs = stot;

#pragma unroll
    for (int r = 0; r < 2; ++r) {
        const int i = tid * 4 + r * 1024;
        const float4 nw = *(const float4*)(norm_w + i);
        *(float4*)(yrow + i) = make_float4(vals[r * 4 + 0] * rs * nw.x,
                                           vals[r * 4 + 1] * rs * nw.y,
                                           vals[r * 4 + 2] * rs * nw.z,
                                           vals[r * 4 + 3] * rs * nw.w);
    }
}

// ---------------- launch -----------------------------------------------------
extern "C" void kernel_launch(void* const* d_in, const int* in_sizes, int n_in,
                              void* d_out, int out_size)
{
    const float* hs      = (const float*)d_in[0];
    const float* W_in    = (const float*)d_in[1];
    const float* conv_w  = (const float*)d_in[2];
    const float* conv_b  = (const float*)d_in[3];
    const float* dt_bias = (const float*)d_in[4];
    const float* A_log   = (const float*)d_in[5];
    const float* D_param = (const float*)d_in[6];
    const float* norm_w  = (const float*)d_in[7];
    const float* W_out   = (const float*)d_in[8];
    float* out = (float*)d_out;

    void *pproj = nullptr, *py = nullptr;
    cudaGetSymbolAddress(&pproj, g_proj);
    cudaGetSymbolAddress(&py, g_y);

    // 1) proj = hs @ W_in^T : M=8192, N=4384, K=2048
    {
        dim3 grid((PROJ + 127) / 128, (B_ * L_) / 128);
        sgemm_nt<1><<<grid, 256>>>(hs, W_in, (float*)pproj, B_ * L_, PROJ, DM);
    }
    // 2) conv + silu
    {
        dim3 grid((CONV_DIM + 255) / 256, B_ * L_);
        conv_kernel<<<grid, 256>>>(conv_w, conv_b);
    }
    // 3) dt / dA
    dt_kernel<<<(B_ * L_ * H_ + 255) / 256, 256>>>(dt_bias, A_log);
    // 4) selective scan
    scan_kernel<<<B_ * H_ * 2, 256>>>();
    // 5) gate + rmsnorm (in place on g_y)
    gate_rms_kernel<<<B_ * L_, 256>>>(D_param, norm_w);
    // 6) out = g @ W_out^T : M=8192, N=2048, K=2048
    {
        dim3 grid(DM / 128, (B_ * L_) / 128);
        sgemm_nt<0><<<grid, 256>>>((const float*)py, W_out, out, B_ * L_, DM, INTER);
    }
}

// round 3
// speedup vs baseline: 1.7363x; 1.7363x over previous
#include <cuda_runtime.h>
#include <cuda_bf16.h>
#include <cstdint>
#include <cstddef>

#define B_ 2
#define L_ 4096
#define DM 2048
#define H_ 32
#define P_ 64
#define N_ 128
#define INTER 2048
#define CONV_DIM 2304
#define PROJ 4384
#define PROJ_PAD 4480
#define EPSV 1e-5f

// ---------------- scratch (__device__ globals; no allocations allowed) ------
__device__ float g_proj[(size_t)B_ * L_ * PROJ_PAD];
__device__ float g_conv[(size_t)B_ * L_ * CONV_DIM];
__device__ float g_y[(size_t)B_ * L_ * INTER];
__device__ float g_dA[B_ * L_ * H_];
__device__ float g_dt[B_ * L_ * H_];
// bf16 split operands
__device__ __nv_bfloat16 g_hs_hi[(size_t)B_ * L_ * DM];
__device__ __nv_bfloat16 g_hs_lo[(size_t)B_ * L_ * DM];
__device__ __nv_bfloat16 g_win_hi[(size_t)PROJ_PAD * DM];
__device__ __nv_bfloat16 g_win_lo[(size_t)PROJ_PAD * DM];
__device__ __nv_bfloat16 g_yh[(size_t)B_ * L_ * INTER];
__device__ __nv_bfloat16 g_yl[(size_t)B_ * L_ * INTER];
__device__ __nv_bfloat16 g_wo_hi[(size_t)DM * INTER];
__device__ __nv_bfloat16 g_wo_lo[(size_t)DM * INTER];

// ---------------- helpers ----------------------------------------------------
__device__ __forceinline__ float siluf(float x) {
    return x * (1.f / (1.f + expf(-x)));
}
__device__ __forceinline__ float softplusf(float x) {
    return (x > 20.f) ? x : log1pf(expf(x));
}
__device__ __forceinline__ uint32_t s2u(const void* p) {
    return (uint32_t)__cvta_generic_to_shared(p);
}
__device__ __forceinline__ void cp_async4(uint32_t saddr, const void* g) {
    asm volatile("cp.async.ca.shared.global [%0], [%1], 4;\n" :: "r"(saddr), "l"(g));
}
__device__ __forceinline__ void cp16(uint32_t saddr, const void* g) {
    asm volatile("cp.async.cg.shared.global [%0], [%1], 16;\n" :: "r"(saddr), "l"(g));
}
__device__ __forceinline__ void cp_commit() {
    asm volatile("cp.async.commit_group;\n" ::: "memory");
}
__device__ __forceinline__ void cp_wait2() {
    asm volatile("cp.async.wait_group 2;\n" ::: "memory");
}

// ---------------- warp-level HMMA plumbing ----------------------------------
__device__ __forceinline__ void ldm_x4(uint32_t* r, uint32_t addr) {
    asm volatile("ldmatrix.sync.aligned.m8n8.x4.shared.b16 {%0,%1,%2,%3}, [%4];"
                 : "=r"(r[0]), "=r"(r[1]), "=r"(r[2]), "=r"(r[3]) : "r"(addr));
}
__device__ __forceinline__ void mma16816(float* d, const uint32_t* a, const uint32_t* b) {
    asm volatile(
        "mma.sync.aligned.m16n8k16.row.col.f32.bf16.bf16.f32 "
        "{%0,%1,%2,%3}, {%4,%5,%6,%7}, {%8,%9}, {%0,%1,%2,%3};"
        : "+f"(d[0]), "+f"(d[1]), "+f"(d[2]), "+f"(d[3])
        : "r"(a[0]), "r"(a[1]), "r"(a[2]), "r"(a[3]), "r"(b[0]), "r"(b[1]));
}

// ---------------- 3-product bf16-split GEMM on HMMA -------------------------
// C[m,n] = sum_k A[m,k]*Bt[n,k];  A = Ah+Al, Bt = Bh+Bl, drop lo*lo.
// CTA tile 128x128, BK=64 bf16 (128B SW128 rows), 3-stage cp.async pipeline.
// 8 warps: warp (wid&1) -> m-half (64), (wid>>1) -> n-quarter (32).
#define STAGE_BYTES 65536
#define GEMM_SMEM_BYTES (3 * STAGE_BYTES)

__global__ __launch_bounds__(256, 1)
void gemm_mma3(const __nv_bfloat16* __restrict__ Ah, const __nv_bfloat16* __restrict__ Al,
               const __nv_bfloat16* __restrict__ Bh, const __nv_bfloat16* __restrict__ Bl,
               float* __restrict__ C, int K, int ldc)
{
    extern __shared__ __align__(1024) char smem[];
    const uint32_t sb = s2u(smem);
    const int tid = threadIdx.x;
    const int wid = tid >> 5;
    const int lane = tid & 31;
    const int bn = blockIdx.x * 128;
    const int bm = blockIdx.y * 128;
    const int chunks = K >> 6;

    const int wm = (wid & 1) * 64;
    const int wn = (wid >> 1) * 32;

    // per-lane ldmatrix address components
    const int rA = wm + (lane & 15);
    const uint32_t selA = (lane & 16) ? 16u : 0u;
    const uint32_t xorA = (uint32_t)((rA & 7) * 16);
    uint32_t rowOffA[4];
#pragma unroll
    for (int mf = 0; mf < 4; ++mf) rowOffA[mf] = (uint32_t)((rA + mf * 16) * 128);

    const int rB = wn + (lane & 7) + ((lane & 16) ? 8 : 0);
    const uint32_t selB = (lane & 8) ? 16u : 0u;
    const uint32_t xorB = (uint32_t)((rB & 7) * 16);
    uint32_t rowOffB[2];
#pragma unroll
    for (int nb = 0; nb < 2; ++nb) rowOffB[nb] = (uint32_t)((rB + nb * 16) * 128);

    // cp.async mapping: per tensor, thread handles 4 chunks (16B each)
    auto issue = [&](int c) {
        const int s = c % 3;
        const uint32_t base = sb + (uint32_t)s * STAGE_BYTES;
        const int k0 = c << 6;
#pragma unroll
        for (int q = 0; q < 4; ++q) {
            const int cc = tid * 4 + q;          // 0..1023
            const int row = cc >> 3;
            const int seg = cc & 7;
            const uint32_t dst = (uint32_t)(row * 128 + ((seg * 16) ^ ((row & 7) * 16)));
            const size_t goffA = (size_t)(bm + row) * K + k0 + seg * 8;
            const size_t goffB = (size_t)(bn + row) * K + k0 + seg * 8;
            cp16(base + 0 * 16384 + dst, Ah + goffA);
            cp16(base + 1 * 16384 + dst, Al + goffA);
            cp16(base + 2 * 16384 + dst, Bh + goffB);
            cp16(base + 3 * 16384 + dst, Bl + goffB);
        }
    };

    float acc[4][4][4];
#pragma unroll
    for (int i = 0; i < 4; ++i)
#pragma unroll
        for (int j = 0; j < 4; ++j)
#pragma unroll
            for (int q = 0; q < 4; ++q) acc[i][j][q] = 0.f;

    issue(0); cp_commit();
    issue(1); cp_commit();

    for (int c = 0; c < chunks; ++c) {
        if (c + 2 < chunks) issue(c + 2);
        cp_commit();
        cp_wait2();
        __syncthreads();

        const uint32_t base = sb + (uint32_t)(c % 3) * STAGE_BYTES;
        const uint32_t bAh = base;
        const uint32_t bAl = base + 16384;
        const uint32_t bBh = base + 32768;
        const uint32_t bBl = base + 49152;

#pragma unroll
        for (int ks = 0; ks < 4; ++ks) {
            const uint32_t cA = ((uint32_t)(ks * 32) + selA) ^ xorA;
            const uint32_t cB = ((uint32_t)(ks * 32) + selB) ^ xorB;
            uint32_t ah[4][4], al[4][4];
#pragma unroll
            for (int mf = 0; mf < 4; ++mf) {
                ldm_x4(ah[mf], bAh + rowOffA[mf] + cA);
                ldm_x4(al[mf], bAl + rowOffA[mf] + cA);
            }
            uint32_t bh[4][2], bl[4][2];
#pragma unroll
            for (int nb = 0; nb < 2; ++nb) {
                uint32_t t[4];
                ldm_x4(t, bBh + rowOffB[nb] + cB);
                bh[nb * 2][0] = t[0]; bh[nb * 2][1] = t[1];
                bh[nb * 2 + 1][0] = t[2]; bh[nb * 2 + 1][1] = t[3];
                ldm_x4(t, bBl + rowOffB[nb] + cB);
                bl[nb * 2][0] = t[0]; bl[nb * 2][1] = t[1];
                bl[nb * 2 + 1][0] = t[2]; bl[nb * 2 + 1][1] = t[3];
            }
#pragma unroll
            for (int mf = 0; mf < 4; ++mf)
#pragma unroll
                for (int nf = 0; nf < 4; ++nf) {
                    mma16816(acc[mf][nf], ah[mf], bh[nf]);
                    mma16816(acc[mf][nf], ah[mf], bl[nf]);
                    mma16816(acc[mf][nf], al[mf], bh[nf]);
                }
        }
        __syncthreads();
    }

    // epilogue: d mapping — lane l: rows g=(l>>2), g+8; cols 2t, 2t+1 (t=l&3)
    const int g = lane >> 2;
    const int t2 = (lane & 3) * 2;
#pragma unroll
    for (int mf = 0; mf < 4; ++mf) {
#pragma unroll
        for (int nf = 0; nf < 4; ++nf) {
            const int col = bn + wn + nf * 8 + t2;
            const int row0 = bm + wm + mf * 16 + g;
            *(float2*)(C + (size_t)row0 * ldc + col) =
                make_float2(acc[mf][nf][0], acc[mf][nf][1]);
            *(float2*)(C + (size_t)(row0 + 8) * ldc + col) =
                make_float2(acc[mf][nf][2], acc[mf][nf][3]);
        }
    }
}

// ---------------- fp32 -> bf16 hi/lo splits ---------------------------------
__global__ __launch_bounds__(256)
void split_kernel(const float* __restrict__ src, __nv_bfloat16* __restrict__ hi,
                  __nv_bfloat16* __restrict__ lo, int n4)
{
    const int i = blockIdx.x * 256 + threadIdx.x;
    if (i >= n4) return;
    const float4 v = ((const float4*)src)[i];
    __nv_bfloat16 h0 = __float2bfloat16(v.x), h1 = __float2bfloat16(v.y);
    __nv_bfloat16 h2 = __float2bfloat16(v.z), h3 = __float2bfloat16(v.w);
    hi[i * 4 + 0] = h0; hi[i * 4 + 1] = h1; hi[i * 4 + 2] = h2; hi[i * 4 + 3] = h3;
    lo[i * 4 + 0] = __float2bfloat16(v.x - __bfloat162float(h0));
    lo[i * 4 + 1] = __float2bfloat16(v.y - __bfloat162float(h1));
    lo[i * 4 + 2] = __float2bfloat16(v.z - __bfloat162float(h2));
    lo[i * 4 + 3] = __float2bfloat16(v.w - __bfloat162float(h3));
}

// W_in split with row padding 4384 -> 4480 (pad rows = 0)
__global__ __launch_bounds__(256)
void split_pad_kernel(const float* __restrict__ src, __nv_bfloat16* __restrict__ hi,
                      __nv_bfloat16* __restrict__ lo)
{
    const int i = blockIdx.x * 256 + threadIdx.x;   // over PROJ_PAD*DM/4
    if (i >= PROJ_PAD * DM / 4) return;
    const int row = i / (DM / 4);
    float4 v = make_float4(0.f, 0.f, 0.f, 0.f);
    if (row < PROJ) v = ((const float4*)src)[i];
    __nv_bfloat16 h0 = __float2bfloat16(v.x), h1 = __float2bfloat16(v.y);
    __nv_bfloat16 h2 = __float2bfloat16(v.z), h3 = __float2bfloat16(v.w);
    hi[i * 4 + 0] = h0; hi[i * 4 + 1] = h1; hi[i * 4 + 2] = h2; hi[i * 4 + 3] = h3;
    lo[i * 4 + 0] = __float2bfloat16(v.x - __bfloat162float(h0));
    lo[i * 4 + 1] = __float2bfloat16(v.y - __bfloat162float(h1));
    lo[i * 4 + 2] = __float2bfloat16(v.z - __bfloat162float(h2));
    lo[i * 4 + 3] = __float2bfloat16(v.w - __bfloat162float(h3));
}

// ---------------- depthwise causal conv (K=4) + bias + SiLU ------------------
__global__ __launch_bounds__(256)
void conv_kernel(const float* __restrict__ conv_w, const float* __restrict__ conv_b)
{
    const int c = blockIdx.x * 256 + threadIdx.x;
    if (c >= CONV_DIM) return;
    const int bl = blockIdx.y;
    const int l = bl & (L_ - 1);
    float acc = conv_b[c];
    const float* w = conv_w + c * 4;
#pragma unroll
    for (int j = 0; j < 4; ++j) {
        const int ll = l - 3 + j;
        if (ll >= 0)
            acc = fmaf(g_proj[(size_t)(bl + j - 3) * PROJ_PAD + INTER + c], w[j], acc);
    }
    g_conv[(size_t)bl * CONV_DIM + c] = siluf(acc);
}

// ---------------- dt = softplus(dt_raw + bias); dA = exp(dt*A) ---------------
__global__ __launch_bounds__(256)
void dt_kernel(const float* __restrict__ dt_bias, const float* __restrict__ A_log)
{
    const int idx = blockIdx.x * 256 + threadIdx.x;
    if (idx >= B_ * L_ * H_) return;
    const int hh = idx & (H_ - 1);
    const int bl = idx >> 5;
    const float x = g_proj[(size_t)bl * PROJ_PAD + INTER + CONV_DIM + hh] + dt_bias[hh];
    const float dt = softplusf(x);
    const float A = -expf(A_log[hh]);
    g_dt[idx] = dt;
    g_dA[idx] = expf(dt * A);
}

// ---------------- selective scan --------------------------------------------
__global__ __launch_bounds__(256)
void scan_kernel()
{
    const int blk = blockIdx.x;
    const int ph = blk & 1;
    const int h = (blk >> 1) & (H_ - 1);
    const int b = blk >> 6;
    const int tid = threadIdx.x;
    const int pg = tid >> 4;
    const int ng = tid & 15;

    __shared__ float sB[4][128];
    __shared__ float sC[4][128];
    __shared__ float sx[4][32];
    __shared__ float sS[4][2];

    auto issue = [&](int t, int s) {
        const float* base = g_conv + (size_t)(b * L_ + t) * CONV_DIM;
        if (tid < 128) cp_async4(s2u(&sB[s][tid]), base + INTER + tid);
        else           cp_async4(s2u(&sC[s][tid - 128]), base + INTER + N_ + (tid - 128));
        if (tid < 32)       cp_async4(s2u(&sx[s][tid]), base + h * P_ + ph * 32 + tid);
        else if (tid == 32) cp_async4(s2u(&sS[s][0]), g_dA + (b * L_ + t) * H_ + h);
        else if (tid == 33) cp_async4(s2u(&sS[s][1]), g_dt + (b * L_ + t) * H_ + h);
    };

    for (int t = 0; t < 3; ++t) { issue(t, t); cp_commit(); }

    float hst[16];
#pragma unroll
    for (int i = 0; i < 16; ++i) hst[i] = 0.f;

    for (int t = 0; t < L_; ++t) {
        cp_wait2();
        __syncthreads();
        if (t + 3 < L_) issue(t + 3, (t + 3) & 3);
        cp_commit();

        const int s = t & 3;
        const float dA = sS[s][0];
        const float dtv = sS[s][1];
        const float2 xp = *(const float2*)&sx[s][pg * 2];
        const float dtx0 = dtv * xp.x;
        const float dtx1 = dtv * xp.y;
        float acc0 = 0.f, acc1 = 0.f;
#pragma unroll
        for (int j = 0; j < 2; ++j) {
            const float4 b4 = *(const float4*)&sB[s][j * 64 + ng * 4];
            const float4 c4 = *(const float4*)&sC[s][j * 64 + ng * 4];
            float* h0 = &hst[j * 4];
            float* h1 = &hst[8 + j * 4];
            h0[0] = fmaf(dA, h0[0], dtx0 * b4.x); acc0 = fmaf(h0[0], c4.x, acc0);
            h0[1] = fmaf(dA, h0[1], dtx0 * b4.y); acc0 = fmaf(h0[1], c4.y, acc0);
            h0[2] = fmaf(dA, h0[2], dtx0 * b4.z); acc0 = fmaf(h0[2], c4.z, acc0);
            h0[3] = fmaf(dA, h0[3], dtx0 * b4.w); acc0 = fmaf(h0[3], c4.w, acc0);
            h1[0] = fmaf(dA, h1[0], dtx1 * b4.x); acc1 = fmaf(h1[0], c4.x, acc1);
            h1[1] = fmaf(dA, h1[1], dtx1 * b4.y); acc1 = fmaf(h1[1], c4.y, acc1);
            h1[2] = fmaf(dA, h1[2], dtx1 * b4.z); acc1 = fmaf(h1[2], c4.z, acc1);
            h1[3] = fmaf(dA, h1[3], dtx1 * b4.w); acc1 = fmaf(h1[3], c4.w, acc1);
        }
#pragma unroll
        for (int o = 8; o; o >>= 1) {
            acc0 += __shfl_xor_sync(0xffffffffu, acc0, o);
            acc1 += __shfl_xor_sync(0xffffffffu, acc1, o);
        }
        if (ng == 0) {
            *(float2*)&g_y[(size_t)(b * L_ + t) * INTER + h * P_ + ph * 32 + pg * 2] =
                make_float2(acc0, acc1);
        }
    }
}

// ---------------- y + D*xs, gate*silu, RMSNorm, fused bf16 split -------------
__global__ __launch_bounds__(256)
void gate_rms_kernel(const float* __restrict__ D_param, const float* __restrict__ norm_w)
{
    const int bl = blockIdx.x;
    const int tid = threadIdx.x;
    const float* yrow = g_y + (size_t)bl * INTER;
    const float* grow = g_proj + (size_t)bl * PROJ_PAD;
    const float* xrow = g_conv + (size_t)bl * CONV_DIM;

    float vals[8];
    float ss = 0.f;
#pragma unroll
    for (int r = 0; r < 2; ++r) {
        const int i = tid * 4 + r * 1024;
        const float4 yv = *(const float4*)(yrow + i);
        const float4 gv = *(const float4*)(grow + i);
        const float4 xv = *(const float4*)(xrow + i);
        const float d = D_param[i >> 6];
        float g0 = (yv.x + d * xv.x) * siluf(gv.x);
        float g1 = (yv.y + d * xv.y) * siluf(gv.y);
        float g2 = (yv.z + d * xv.z) * siluf(gv.z);
        float g3 = (yv.w + d * xv.w) * siluf(gv.w);
        vals[r * 4 + 0] = g0; vals[r * 4 + 1] = g1;
        vals[r * 4 + 2] = g2; vals[r * 4 + 3] = g3;
        ss += g0 * g0 + g1 * g1 + g2 * g2 + g3 * g3;
    }

    __shared__ float red[8];
    __shared__ float stot;
#pragma unroll
    for (int o = 16; o; o >>= 1) ss += __shfl_xor_sync(0xffffffffu, ss, o);
    if ((tid & 31) == 0) red[tid >> 5] = ss;
    __syncthreads();
    if (tid == 0) {
        float v = 0.f;
#pragma unroll
        for (int i = 0; i < 8; ++i) v += red[i];
        stot = rsqrtf(v * (1.f / (float)INTER) + EPSV);
    }
    __syncthreads();
    const float rs = stot;

    __nv_bfloat16* yh = g_yh + (size_t)bl * INTER;
    __nv_bfloat16* yl = g_yl + (size_t)bl * INTER;
#pragma unroll
    for (int r = 0; r < 2; ++r) {
        const int i = tid * 4 + r * 1024;
        const float4 nw = *(const float4*)(norm_w + i);
        float o0 = vals[r * 4 + 0] * rs * nw.x;
        float o1 = vals[r * 4 + 1] * rs * nw.y;
        float o2 = vals[r * 4 + 2] * rs * nw.z;
        float o3 = vals[r * 4 + 3] * rs * nw.w;
        __nv_bfloat16 h0 = __float2bfloat16(o0), h1 = __float2bfloat16(o1);
        __nv_bfloat16 h2 = __float2bfloat16(o2), h3 = __float2bfloat16(o3);
        yh[i + 0] = h0; yh[i + 1] = h1; yh[i + 2] = h2; yh[i + 3] = h3;
        yl[i + 0] = __float2bfloat16(o0 - __bfloat162float(h0));
        yl[i + 1] = __float2bfloat16(o1 - __bfloat162float(h1));
        yl[i + 2] = __float2bfloat16(o2 - __bfloat162float(h2));
        yl[i + 3] = __float2bfloat16(o3 - __bfloat162float(h3));
    }
}

// ---------------- launch -----------------------------------------------------
extern "C" void kernel_launch(void* const* d_in, const int* in_sizes, int n_in,
                              void* d_out, int out_size)
{
    const float* hs      = (const float*)d_in[0];
    const float* W_in    = (const float*)d_in[1];
    const float* conv_w  = (const float*)d_in[2];
    const float* conv_b  = (const float*)d_in[3];
    const float* dt_bias = (const float*)d_in[4];
    const float* A_log   = (const float*)d_in[5];
    const float* D_param = (const float*)d_in[6];
    const float* norm_w  = (const float*)d_in[7];
    const float* W_out   = (const float*)d_in[8];
    float* out = (float*)d_out;

    cudaFuncSetAttribute(gemm_mma3, cudaFuncAttributeMaxDynamicSharedMemorySize,
                         GEMM_SMEM_BYTES);

    void *pproj = nullptr;
    void *phh = nullptr, *phl = nullptr, *pwh = nullptr, *pwl = nullptr;
    void *pyh = nullptr, *pyl = nullptr, *poh = nullptr, *pol = nullptr;
    cudaGetSymbolAddress(&pproj, g_proj);
    cudaGetSymbolAddress(&phh, g_hs_hi);
    cudaGetSymbolAddress(&phl, g_hs_lo);
    cudaGetSymbolAddress(&pwh, g_win_hi);
    cudaGetSymbolAddress(&pwl, g_win_lo);
    cudaGetSymbolAddress(&pyh, g_yh);
    cudaGetSymbolAddress(&pyl, g_yl);
    cudaGetSymbolAddress(&poh, g_wo_hi);
    cudaGetSymbolAddress(&pol, g_wo_lo);

    // 0) splits
    {
        const int n4 = B_ * L_ * DM / 4;
        split_kernel<<<(n4 + 255) / 256, 256>>>(hs, (__nv_bfloat16*)phh, (__nv_bfloat16*)phl, n4);
    }
    split_pad_kernel<<<(PROJ_PAD * DM / 4 + 255) / 256, 256>>>(
        W_in, (__nv_bfloat16*)pwh, (__nv_bfloat16*)pwl);
    {
        const int n4 = DM * INTER / 4;
        split_kernel<<<(n4 + 255) / 256, 256>>>(W_out, (__nv_bfloat16*)poh, (__nv_bfloat16*)pol, n4);
    }

    // 1) proj = hs @ W_in^T  (HMMA split-3, N padded to 4480)
    {
        dim3 grid(PROJ_PAD / 128, (B_ * L_) / 128);
        gemm_mma3<<<grid, 256, GEMM_SMEM_BYTES>>>(
            (const __nv_bfloat16*)phh, (const __nv_bfloat16*)phl,
            (const __nv_bfloat16*)pwh, (const __nv_bfloat16*)pwl,
            (float*)pproj, DM, PROJ_PAD);
    }
    // 2) conv + silu
    {
        dim3 grid((CONV_DIM + 255) / 256, B_ * L_);
        conv_kernel<<<grid, 256>>>(conv_w, conv_b);
    }
    // 3) dt / dA
    dt_kernel<<<(B_ * L_ * H_ + 255) / 256, 256>>>(dt_bias, A_log);
    // 4) selective scan
    scan_kernel<<<B_ * H_ * 2, 256>>>();
    // 5) gate + rmsnorm + split
    gate_rms_kernel<<<B_ * L_, 256>>>(D_param, norm_w);
    // 6) out = g @ W_out^T
    {
        dim3 grid(DM / 128, (B_ * L_) / 128);
        gemm_mma3<<<grid, 256, GEMM_SMEM_BYTES>>>(
            (const __nv_bfloat16*)pyh, (const __nv_bfloat16*)pyl,
            (const __nv_bfloat16*)poh, (const __nv_bfloat16*)pol,
            out, INTER, DM);
    }
}

// round 4
// speedup vs baseline: 1.8010x; 1.0373x over previous
#include <cuda_runtime.h>
#include <cuda_bf16.h>
#include <cstdint>
#include <cstddef>

#define B_ 2
#define L_ 4096
#define DM 2048
#define H_ 32
#define P_ 64
#define N_ 128
#define INTER 2048
#define CONV_DIM 2304
#define PROJ 4384
#define PROJ_PAD 4480
#define EPSV 1e-5f

// ---------------- scratch (__device__ globals; no allocations allowed) ------
__device__ float g_proj[(size_t)B_ * L_ * PROJ_PAD];
__device__ float g_conv[(size_t)B_ * L_ * CONV_DIM];
__device__ float g_y[(size_t)B_ * L_ * INTER];
__device__ float g_dA[B_ * L_ * H_];
__device__ float g_dt[B_ * L_ * H_];
// bf16 split operands
__device__ __nv_bfloat16 g_hs_hi[(size_t)B_ * L_ * DM];
__device__ __nv_bfloat16 g_hs_lo[(size_t)B_ * L_ * DM];
__device__ __nv_bfloat16 g_win_hi[(size_t)PROJ_PAD * DM];
__device__ __nv_bfloat16 g_win_lo[(size_t)PROJ_PAD * DM];
__device__ __nv_bfloat16 g_yh[(size_t)B_ * L_ * INTER];
__device__ __nv_bfloat16 g_yl[(size_t)B_ * L_ * INTER];
__device__ __nv_bfloat16 g_wo_hi[(size_t)DM * INTER];
__device__ __nv_bfloat16 g_wo_lo[(size_t)DM * INTER];

// ---------------- helpers ----------------------------------------------------
__device__ __forceinline__ float siluf(float x) {
    return x * (1.f / (1.f + expf(-x)));
}
__device__ __forceinline__ float softplusf(float x) {
    return (x > 20.f) ? x : log1pf(expf(x));
}
__device__ __forceinline__ uint32_t s2u(const void* p) {
    return (uint32_t)__cvta_generic_to_shared(p);
}
__device__ __forceinline__ void cp_async4(uint32_t saddr, const void* g) {
    asm volatile("cp.async.ca.shared.global [%0], [%1], 4;\n" :: "r"(saddr), "l"(g));
}
__device__ __forceinline__ void cp16(uint32_t saddr, const void* g) {
    asm volatile("cp.async.cg.shared.global [%0], [%1], 16;\n" :: "r"(saddr), "l"(g));
}
__device__ __forceinline__ void cp_commit() {
    asm volatile("cp.async.commit_group;\n" ::: "memory");
}
__device__ __forceinline__ void cp_wait2() {
    asm volatile("cp.async.wait_group 2;\n" ::: "memory");
}

// ---------------- warp-level HMMA plumbing ----------------------------------
__device__ __forceinline__ void ldm_x4(uint32_t* r, uint32_t addr) {
    asm volatile("ldmatrix.sync.aligned.m8n8.x4.shared.b16 {%0,%1,%2,%3}, [%4];"
                 : "=r"(r[0]), "=r"(r[1]), "=r"(r[2]), "=r"(r[3]) : "r"(addr));
}
__device__ __forceinline__ void mma16816(float* d, const uint32_t* a, const uint32_t* b) {
    asm volatile(
        "mma.sync.aligned.m16n8k16.row.col.f32.bf16.bf16.f32 "
        "{%0,%1,%2,%3}, {%4,%5,%6,%7}, {%8,%9}, {%0,%1,%2,%3};"
        : "+f"(d[0]), "+f"(d[1]), "+f"(d[2]), "+f"(d[3])
        : "r"(a[0]), "r"(a[1]), "r"(a[2]), "r"(a[3]), "r"(b[0]), "r"(b[1]));
}

// ---------------- 3-product bf16-split GEMM on HMMA -------------------------
// C[m,n] = sum_k A[m,k]*Bt[n,k];  A = Ah+Al, Bt = Bh+Bl, drop lo*lo.
// CTA tile 128x128, BK=64 bf16 (128B SW128 rows), 3-stage cp.async pipeline.
// 16 warps (512 thr): warp (wid&3) -> m-32-slice, (wid>>2) -> n-32-slice.
#define STAGE_BYTES 65536
#define GEMM_SMEM_BYTES (3 * STAGE_BYTES)

__global__ __launch_bounds__(512, 1)
void gemm_mma3(const __nv_bfloat16* __restrict__ Ah, const __nv_bfloat16* __restrict__ Al,
               const __nv_bfloat16* __restrict__ Bh, const __nv_bfloat16* __restrict__ Bl,
               float* __restrict__ C, int K, int ldc)
{
    extern __shared__ __align__(1024) char smem[];
    const uint32_t sb = s2u(smem);
    const int tid = threadIdx.x;
    const int wid = tid >> 5;
    const int lane = tid & 31;
    const int bn = blockIdx.x * 128;
    const int bm = blockIdx.y * 128;
    const int chunks = K >> 6;

    const int wm = (wid & 3) * 32;
    const int wn = (wid >> 2) * 32;

    // per-lane ldmatrix address components
    const int rA = wm + (lane & 15);
    const uint32_t selA = (lane & 16) ? 16u : 0u;
    const uint32_t xorA = (uint32_t)((rA & 7) * 16);
    uint32_t rowOffA[2];
#pragma unroll
    for (int mf = 0; mf < 2; ++mf) rowOffA[mf] = (uint32_t)((rA + mf * 16) * 128);

    const int rB = wn + (lane & 7) + ((lane & 16) ? 8 : 0);
    const uint32_t selB = (lane & 8) ? 16u : 0u;
    const uint32_t xorB = (uint32_t)((rB & 7) * 16);
    uint32_t rowOffB[2];
#pragma unroll
    for (int nb = 0; nb < 2; ++nb) rowOffB[nb] = (uint32_t)((rB + nb * 16) * 128);

    // cp.async mapping: per tensor, thread handles 2 chunks (16B each)
    auto issue = [&](int c) {
        const int s = c % 3;
        const uint32_t base = sb + (uint32_t)s * STAGE_BYTES;
        const int k0 = c << 6;
#pragma unroll
        for (int q = 0; q < 2; ++q) {
            const int cc = tid * 2 + q;          // 0..1023
            const int row = cc >> 3;
            const int seg = cc & 7;
            const uint32_t dst = (uint32_t)(row * 128 + ((seg * 16) ^ ((row & 7) * 16)));
            const size_t goffA = (size_t)(bm + row) * K + k0 + seg * 8;
            const size_t goffB = (size_t)(bn + row) * K + k0 + seg * 8;
            cp16(base + 0 * 16384 + dst, Ah + goffA);
            cp16(base + 1 * 16384 + dst, Al + goffA);
            cp16(base + 2 * 16384 + dst, Bh + goffB);
            cp16(base + 3 * 16384 + dst, Bl + goffB);
        }
    };

    float acc[2][4][4];
#pragma unroll
    for (int i = 0; i < 2; ++i)
#pragma unroll
        for (int j = 0; j < 4; ++j)
#pragma unroll
            for (int q = 0; q < 4; ++q) acc[i][j][q] = 0.f;

    issue(0); cp_commit();
    issue(1); cp_commit();

    for (int c = 0; c < chunks; ++c) {
        if (c + 2 < chunks) issue(c + 2);
        cp_commit();
        cp_wait2();
        __syncthreads();

        const uint32_t base = sb + (uint32_t)(c % 3) * STAGE_BYTES;
        const uint32_t bAh = base;
        const uint32_t bAl = base + 16384;
        const uint32_t bBh = base + 32768;
        const uint32_t bBl = base + 49152;

#pragma unroll
        for (int ks = 0; ks < 4; ++ks) {
            const uint32_t cA = ((uint32_t)(ks * 32) + selA) ^ xorA;
            const uint32_t cB = ((uint32_t)(ks * 32) + selB) ^ xorB;
            uint32_t ah[2][4], al[2][4];
#pragma unroll
            for (int mf = 0; mf < 2; ++mf) {
                ldm_x4(ah[mf], bAh + rowOffA[mf] + cA);
                ldm_x4(al[mf], bAl + rowOffA[mf] + cA);
            }
            uint32_t bh[4][2], bl[4][2];
#pragma unroll
            for (int nb = 0; nb < 2; ++nb) {
                uint32_t t[4];
                ldm_x4(t, bBh + rowOffB[nb] + cB);
                bh[nb * 2][0] = t[0]; bh[nb * 2][1] = t[1];
                bh[nb * 2 + 1][0] = t[2]; bh[nb * 2 + 1][1] = t[3];
                ldm_x4(t, bBl + rowOffB[nb] + cB);
                bl[nb * 2][0] = t[0]; bl[nb * 2][1] = t[1];
                bl[nb * 2 + 1][0] = t[2]; bl[nb * 2 + 1][1] = t[3];
            }
#pragma unroll
            for (int mf = 0; mf < 2; ++mf)
#pragma unroll
                for (int nf = 0; nf < 4; ++nf) {
                    mma16816(acc[mf][nf], ah[mf], bh[nf]);
                    mma16816(acc[mf][nf], ah[mf], bl[nf]);
                    mma16816(acc[mf][nf], al[mf], bh[nf]);
                }
        }
        __syncthreads();
    }

    // epilogue: d mapping — lane l: rows g=(l>>2), g+8; cols 2t, 2t+1 (t=l&3)
    const int g = lane >> 2;
    const int t2 = (lane & 3) * 2;
#pragma unroll
    for (int mf = 0; mf < 2; ++mf) {
#pragma unroll
        for (int nf = 0; nf < 4; ++nf) {
            const int col = bn + wn + nf * 8 + t2;
            const int row0 = bm + wm + mf * 16 + g;
            *(float2*)(C + (size_t)row0 * ldc + col) =
                make_float2(acc[mf][nf][0], acc[mf][nf][1]);
            *(float2*)(C + (size_t)(row0 + 8) * ldc + col) =
                make_float2(acc[mf][nf][2], acc[mf][nf][3]);
        }
    }
}

// ---------------- fp32 -> bf16 hi/lo splits ---------------------------------
__global__ __launch_bounds__(256)
void split_kernel(const float* __restrict__ src, __nv_bfloat16* __restrict__ hi,
                  __nv_bfloat16* __restrict__ lo, int n4)
{
    const int i = blockIdx.x * 256 + threadIdx.x;
    if (i >= n4) return;
    const float4 v = ((const float4*)src)[i];
    __nv_bfloat16 h0 = __float2bfloat16(v.x), h1 = __float2bfloat16(v.y);
    __nv_bfloat16 h2 = __float2bfloat16(v.z), h3 = __float2bfloat16(v.w);
    hi[i * 4 + 0] = h0; hi[i * 4 + 1] = h1; hi[i * 4 + 2] = h2; hi[i * 4 + 3] = h3;
    lo[i * 4 + 0] = __float2bfloat16(v.x - __bfloat162float(h0));
    lo[i * 4 + 1] = __float2bfloat16(v.y - __bfloat162float(h1));
    lo[i * 4 + 2] = __float2bfloat16(v.z - __bfloat162float(h2));
    lo[i * 4 + 3] = __float2bfloat16(v.w - __bfloat162float(h3));
}

// W_in split with row padding 4384 -> 4480 (pad rows = 0)
__global__ __launch_bounds__(256)
void split_pad_kernel(const float* __restrict__ src, __nv_bfloat16* __restrict__ hi,
                      __nv_bfloat16* __restrict__ lo)
{
    const int i = blockIdx.x * 256 + threadIdx.x;   // over PROJ_PAD*DM/4
    if (i >= PROJ_PAD * DM / 4) return;
    const int row = i / (DM / 4);
    float4 v = make_float4(0.f, 0.f, 0.f, 0.f);
    if (row < PROJ) v = ((const float4*)src)[i];
    __nv_bfloat16 h0 = __float2bfloat16(v.x), h1 = __float2bfloat16(v.y);
    __nv_bfloat16 h2 = __float2bfloat16(v.z), h3 = __float2bfloat16(v.w);
    hi[i * 4 + 0] = h0; hi[i * 4 + 1] = h1; hi[i * 4 + 2] = h2; hi[i * 4 + 3] = h3;
    lo[i * 4 + 0] = __float2bfloat16(v.x - __bfloat162float(h0));
    lo[i * 4 + 1] = __float2bfloat16(v.y - __bfloat162float(h1));
    lo[i * 4 + 2] = __float2bfloat16(v.z - __bfloat162float(h2));
    lo[i * 4 + 3] = __float2bfloat16(v.w - __bfloat162float(h3));
}

// ---------------- depthwise causal conv (K=4) + bias + SiLU ------------------
__global__ __launch_bounds__(256)
void conv_kernel(const float* __restrict__ conv_w, const float* __restrict__ conv_b)
{
    const int c = blockIdx.x * 256 + threadIdx.x;
    if (c >= CONV_DIM) return;
    const int bl = blockIdx.y;
    const int l = bl & (L_ - 1);
    float acc = conv_b[c];
    const float* w = conv_w + c * 4;
#pragma unroll
    for (int j = 0; j < 4; ++j) {
        const int ll = l - 3 + j;
        if (ll >= 0)
            acc = fmaf(g_proj[(size_t)(bl + j - 3) * PROJ_PAD + INTER + c], w[j], acc);
    }
    g_conv[(size_t)bl * CONV_DIM + c] = siluf(acc);
}

// ---------------- dt = softplus(dt_raw + bias); dA = exp(dt*A) ---------------
__global__ __launch_bounds__(256)
void dt_kernel(const float* __restrict__ dt_bias, const float* __restrict__ A_log)
{
    const int idx = blockIdx.x * 256 + threadIdx.x;
    if (idx >= B_ * L_ * H_) return;
    const int hh = idx & (H_ - 1);
    const int bl = idx >> 5;
    const float x = g_proj[(size_t)bl * PROJ_PAD + INTER + CONV_DIM + hh] + dt_bias[hh];
    const float dt = softplusf(x);
    const float A = -expf(A_log[hh]);
    g_dt[idx] = dt;
    g_dA[idx] = expf(dt * A);
}

// ---------------- selective scan --------------------------------------------
// Block = (b, h, p-quarter): 256 blocks -> 2 blocks/SM.
// 256 threads: pg (0..15) x ng (0..15). Thread owns p = pq*16+pg, and 8 n
// values at stride 16 (n = ng + 16j) -> conflict-free broadcast LDS.
__global__ __launch_bounds__(256)
void scan_kernel()
{
    const int blk = blockIdx.x;           // 0..255
    const int pq = blk & 3;
    const int h = (blk >> 2) & (H_ - 1);
    const int b = blk >> 7;
    const int tid = threadIdx.x;
    const int pg = tid >> 4;
    const int ng = tid & 15;

    __shared__ float sB[4][128];
    __shared__ float sC[4][128];
    __shared__ float sx[4][16];
    __shared__ float sS[4][2];

    auto issue = [&](int t, int s) {
        const float* base = g_conv + (size_t)(b * L_ + t) * CONV_DIM;
        if (tid < 128) cp_async4(s2u(&sB[s][tid]), base + INTER + tid);
        else           cp_async4(s2u(&sC[s][tid - 128]), base + INTER + N_ + (tid - 128));
        if (tid < 16)       cp_async4(s2u(&sx[s][tid]), base + h * P_ + pq * 16 + tid);
        else if (tid == 16) cp_async4(s2u(&sS[s][0]), g_dA + (b * L_ + t) * H_ + h);
        else if (tid == 17) cp_async4(s2u(&sS[s][1]), g_dt + (b * L_ + t) * H_ + h);
    };

    for (int t = 0; t < 3; ++t) { issue(t, t); cp_commit(); }

    float hst[8];
#pragma unroll
    for (int i = 0; i < 8; ++i) hst[i] = 0.f;

    for (int t = 0; t < L_; ++t) {
        cp_wait2();
        __syncthreads();
        if (t + 3 < L_) issue(t + 3, (t + 3) & 3);
        cp_commit();

        const int s = t & 3;
        const float dA = sS[s][0];
        const float dtv = sS[s][1];
        const float dtx = dtv * sx[s][pg];
        float acc = 0.f;
#pragma unroll
        for (int j = 0; j < 8; ++j) {
            const float bv = sB[s][ng + j * 16];
            const float cv = sC[s][ng + j * 16];
            hst[j] = fmaf(dA, hst[j], dtx * bv);
            acc = fmaf(hst[j], cv, acc);
        }
#pragma unroll
        for (int o = 8; o; o >>= 1)
            acc += __shfl_xor_sync(0xffffffffu, acc, o);
        if (ng == 0)
            g_y[(size_t)(b * L_ + t) * INTER + h * P_ + pq * 16 + pg] = acc;
    }
}

// ---------------- y + D*xs, gate*silu, RMSNorm, fused bf16 split -------------
__global__ __launch_bounds__(256)
void gate_rms_kernel(const float* __restrict__ D_param, const float* __restrict__ norm_w)
{
    const int bl = blockIdx.x;
    const int tid = threadIdx.x;
    const float* yrow = g_y + (size_t)bl * INTER;
    const float* grow = g_proj + (size_t)bl * PROJ_PAD;
    const float* xrow = g_conv + (size_t)bl * CONV_DIM;

    float vals[8];
    float ss = 0.f;
#pragma unroll
    for (int r = 0; r < 2; ++r) {
        const int i = tid * 4 + r * 1024;
        const float4 yv = *(const float4*)(yrow + i);
        const float4 gv = *(const float4*)(grow + i);
        const float4 xv = *(const float4*)(xrow + i);
        const float d = D_param[i >> 6];
        float g0 = (yv.x + d * xv.x) * siluf(gv.x);
        float g1 = (yv.y + d * xv.y) * siluf(gv.y);
        float g2 = (yv.z + d * xv.z) * siluf(gv.z);
        float g3 = (yv.w + d * xv.w) * siluf(gv.w);
        vals[r * 4 + 0] = g0; vals[r * 4 + 1] = g1;
        vals[r * 4 + 2] = g2; vals[r * 4 + 3] = g3;
        ss += g0 * g0 + g1 * g1 + g2 * g2 + g3 * g3;
    }

    __shared__ float red[8];
    __shared__ float stot;
#pragma unroll
    for (int o = 16; o; o >>= 1) ss += __shfl_xor_sync(0xffffffffu, ss, o);
    if ((tid & 31) == 0) red[tid >> 5] = ss;
    __syncthreads();
    if (tid == 0) {
        float v = 0.f;
#pragma unroll
        for (int i = 0; i < 8; ++i) v += red[i];
        stot = rsqrtf(v * (1.f / (float)INTER) + EPSV);
    }
    __syncthreads();
    const float rs = stot;

    __nv_bfloat16* yh = g_yh + (size_t)bl * INTER;
    __nv_bfloat16* yl = g_yl + (size_t)bl * INTER;
#pragma unroll
    for (int r = 0; r < 2; ++r) {
        const int i = tid * 4 + r * 1024;
        const float4 nw = *(const float4*)(norm_w + i);
        float o0 = vals[r * 4 + 0] * rs * nw.x;
        float o1 = vals[r * 4 + 1] * rs * nw.y;
        float o2 = vals[r * 4 + 2] * rs * nw.z;
        float o3 = vals[r * 4 + 3] * rs * nw.w;
        __nv_bfloat16 h0 = __float2bfloat16(o0), h1 = __float2bfloat16(o1);
        __nv_bfloat16 h2 = __float2bfloat16(o2), h3 = __float2bfloat16(o3);
        yh[i + 0] = h0; yh[i + 1] = h1; yh[i + 2] = h2; yh[i + 3] = h3;
        yl[i + 0] = __float2bfloat16(o0 - __bfloat162float(h0));
        yl[i + 1] = __float2bfloat16(o1 - __bfloat162float(h1));
        yl[i + 2] = __float2bfloat16(o2 - __bfloat162float(h2));
        yl[i + 3] = __float2bfloat16(o3 - __bfloat162float(h3));
    }
}

// ---------------- launch -----------------------------------------------------
extern "C" void kernel_launch(void* const* d_in, const int* in_sizes, int n_in,
                              void* d_out, int out_size)
{
    const float* hs      = (const float*)d_in[0];
    const float* W_in    = (const float*)d_in[1];
    const float* conv_w  = (const float*)d_in[2];
    const float* conv_b  = (const float*)d_in[3];
    const float* dt_bias = (const float*)d_in[4];
    const float* A_log   = (const float*)d_in[5];
    const float* D_param = (const float*)d_in[6];
    const float* norm_w  = (const float*)d_in[7];
    const float* W_out   = (const float*)d_in[8];
    float* out = (float*)d_out;

    cudaFuncSetAttribute(gemm_mma3, cudaFuncAttributeMaxDynamicSharedMemorySize,
                         GEMM_SMEM_BYTES);

    void *pproj = nullptr;
    void *phh = nullptr, *phl = nullptr, *pwh = nullptr, *pwl = nullptr;
    void *pyh = nullptr, *pyl = nullptr, *poh = nullptr, *pol = nullptr;
    cudaGetSymbolAddress(&pproj, g_proj);
    cudaGetSymbolAddress(&phh, g_hs_hi);
    cudaGetSymbolAddress(&phl, g_hs_lo);
    cudaGetSymbolAddress(&pwh, g_win_hi);
    cudaGetSymbolAddress(&pwl, g_win_lo);
    cudaGetSymbolAddress(&pyh, g_yh);
    cudaGetSymbolAddress(&pyl, g_yl);
    cudaGetSymbolAddress(&poh, g_wo_hi);
    cudaGetSymbolAddress(&pol, g_wo_lo);

    // 0) splits
    {
        const int n4 = B_ * L_ * DM / 4;
        split_kernel<<<(n4 + 255) / 256, 256>>>(hs, (__nv_bfloat16*)phh, (__nv_bfloat16*)phl, n4);
    }
    split_pad_kernel<<<(PROJ_PAD * DM / 4 + 255) / 256, 256>>>(
        W_in, (__nv_bfloat16*)pwh, (__nv_bfloat16*)pwl);
    {
        const int n4 = DM * INTER / 4;
        split_kernel<<<(n4 + 255) / 256, 256>>>(W_out, (__nv_bfloat16*)poh, (__nv_bfloat16*)pol, n4);
    }

    // 1) proj = hs @ W_in^T  (HMMA split-3, N padded to 4480)
    {
        dim3 grid(PROJ_PAD / 128, (B_ * L_) / 128);
        gemm_mma3<<<grid, 512, GEMM_SMEM_BYTES>>>(
            (const __nv_bfloat16*)phh, (const __nv_bfloat16*)phl,
            (const __nv_bfloat16*)pwh, (const __nv_bfloat16*)pwl,
            (float*)pproj, DM, PROJ_PAD);
    }
    // 2) conv + silu
    {
        dim3 grid((CONV_DIM + 255) / 256, B_ * L_);
        conv_kernel<<<grid, 256>>>(conv_w, conv_b);
    }
    // 3) dt / dA
    dt_kernel<<<(B_ * L_ * H_ + 255) / 256, 256>>>(dt_bias, A_log);
    // 4) selective scan (2 blocks/SM)
    scan_kernel<<<B_ * H_ * 4, 256>>>();
    // 5) gate + rmsnorm + split
    gate_rms_kernel<<<B_ * L_, 256>>>(D_param, norm_w);
    // 6) out = g @ W_out^T
    {
        dim3 grid(DM / 128, (B_ * L_) / 128);
        gemm_mma3<<<grid, 512, GEMM_SMEM_BYTES>>>(
            (const __nv_bfloat16*)pyh, (const __nv_bfloat16*)pyl,
            (const __nv_bfloat16*)poh, (const __nv_bfloat16*)pol,
            out, INTER, DM);
    }
}

// round 5
// speedup vs baseline: 2.5320x; 1.4059x over previous
#include <cuda_runtime.h>
#include <cuda_bf16.h>
#include <cstdint>
#include <cstddef>

#define B_ 2
#define L_ 4096
#define DM 2048
#define H_ 32
#define P_ 64
#define N_ 128
#define INTER 2048
#define CONV_DIM 2304
#define PROJ 4384
#define PROJ_PAD 4480
#define EPSV 1e-5f
#define NCHUNK 32
#define TCH 128

// ---------------- scratch (__device__ globals; no allocations allowed) ------
__device__ float g_proj[(size_t)B_ * L_ * PROJ_PAD];
__device__ float g_conv[(size_t)B_ * L_ * CONV_DIM];
__device__ float g_y[(size_t)B_ * L_ * INTER];
__device__ float g_dA[B_ * L_ * H_];
__device__ float g_dt[B_ * L_ * H_];
// chunked-scan scratch
__device__ float g_state[(size_t)B_ * NCHUNK * H_ * P_ * N_];  // chunk end states
__device__ float g_init[(size_t)B_ * NCHUNK * H_ * P_ * N_];   // chunk start states
__device__ float g_adec[B_ * NCHUNK * H_];
// bf16 split operands
__device__ __nv_bfloat16 g_hs_hi[(size_t)B_ * L_ * DM];
__device__ __nv_bfloat16 g_hs_lo[(size_t)B_ * L_ * DM];
__device__ __nv_bfloat16 g_win_hi[(size_t)PROJ_PAD * DM];
__device__ __nv_bfloat16 g_win_lo[(size_t)PROJ_PAD * DM];
__device__ __nv_bfloat16 g_yh[(size_t)B_ * L_ * INTER];
__device__ __nv_bfloat16 g_yl[(size_t)B_ * L_ * INTER];
__device__ __nv_bfloat16 g_wo_hi[(size_t)DM * INTER];
__device__ __nv_bfloat16 g_wo_lo[(size_t)DM * INTER];

// ---------------- helpers ----------------------------------------------------
__device__ __forceinline__ float siluf(float x) {
    return x * (1.f / (1.f + expf(-x)));
}
__device__ __forceinline__ float softplusf(float x) {
    return (x > 20.f) ? x : log1pf(expf(x));
}
__device__ __forceinline__ uint32_t s2u(const void* p) {
    return (uint32_t)__cvta_generic_to_shared(p);
}
__device__ __forceinline__ void cp_async4(uint32_t saddr, const void* g) {
    asm volatile("cp.async.ca.shared.global [%0], [%1], 4;\n" :: "r"(saddr), "l"(g));
}
__device__ __forceinline__ void cp16(uint32_t saddr, const void* g) {
    asm volatile("cp.async.cg.shared.global [%0], [%1], 16;\n" :: "r"(saddr), "l"(g));
}
__device__ __forceinline__ void cp_commit() {
    asm volatile("cp.async.commit_group;\n" ::: "memory");
}
__device__ __forceinline__ void cp_wait2() {
    asm volatile("cp.async.wait_group 2;\n" ::: "memory");
}

// ---------------- warp-level HMMA plumbing ----------------------------------
__device__ __forceinline__ void ldm_x4(uint32_t* r, uint32_t addr) {
    asm volatile("ldmatrix.sync.aligned.m8n8.x4.shared.b16 {%0,%1,%2,%3}, [%4];"
                 : "=r"(r[0]), "=r"(r[1]), "=r"(r[2]), "=r"(r[3]) : "r"(addr));
}
__device__ __forceinline__ void mma16816(float* d, const uint32_t* a, const uint32_t* b) {
    asm volatile(
        "mma.sync.aligned.m16n8k16.row.col.f32.bf16.bf16.f32 "
        "{%0,%1,%2,%3}, {%4,%5,%6,%7}, {%8,%9}, {%0,%1,%2,%3};"
        : "+f"(d[0]), "+f"(d[1]), "+f"(d[2]), "+f"(d[3])
        : "r"(a[0]), "r"(a[1]), "r"(a[2]), "r"(a[3]), "r"(b[0]), "r"(b[1]));
}

// ---------------- 3-product bf16-split GEMM on HMMA -------------------------
#define STAGE_BYTES 65536
#define GEMM_SMEM_BYTES (3 * STAGE_BYTES)

__global__ __launch_bounds__(512, 1)
void gemm_mma3(const __nv_bfloat16* __restrict__ Ah, const __nv_bfloat16* __restrict__ Al,
               const __nv_bfloat16* __restrict__ Bh, const __nv_bfloat16* __restrict__ Bl,
               float* __restrict__ C, int K, int ldc)
{
    extern __shared__ __align__(1024) char smem[];
    const uint32_t sb = s2u(smem);
    const int tid = threadIdx.x;
    const int wid = tid >> 5;
    const int lane = tid & 31;
    const int bn = blockIdx.x * 128;
    const int bm = blockIdx.y * 128;
    const int chunks = K >> 6;

    const int wm = (wid & 3) * 32;
    const int wn = (wid >> 2) * 32;

    const int rA = wm + (lane & 15);
    const uint32_t selA = (lane & 16) ? 16u : 0u;
    const uint32_t xorA = (uint32_t)((rA & 7) * 16);
    uint32_t rowOffA[2];
#pragma unroll
    for (int mf = 0; mf < 2; ++mf) rowOffA[mf] = (uint32_t)((rA + mf * 16) * 128);

    const int rB = wn + (lane & 7) + ((lane & 16) ? 8 : 0);
    const uint32_t selB = (lane & 8) ? 16u : 0u;
    const uint32_t xorB = (uint32_t)((rB & 7) * 16);
    uint32_t rowOffB[2];
#pragma unroll
    for (int nb = 0; nb < 2; ++nb) rowOffB[nb] = (uint32_t)((rB + nb * 16) * 128);

    auto issue = [&](int c) {
        const int s = c % 3;
        const uint32_t base = sb + (uint32_t)s * STAGE_BYTES;
        const int k0 = c << 6;
#pragma unroll
        for (int q = 0; q < 2; ++q) {
            const int cc = tid * 2 + q;
            const int row = cc >> 3;
            const int seg = cc & 7;
            const uint32_t dst = (uint32_t)(row * 128 + ((seg * 16) ^ ((row & 7) * 16)));
            const size_t goffA = (size_t)(bm + row) * K + k0 + seg * 8;
            const size_t goffB = (size_t)(bn + row) * K + k0 + seg * 8;
            cp16(base + 0 * 16384 + dst, Ah + goffA);
            cp16(base + 1 * 16384 + dst, Al + goffA);
            cp16(base + 2 * 16384 + dst, Bh + goffB);
            cp16(base + 3 * 16384 + dst, Bl + goffB);
        }
    };

    float acc[2][4][4];
#pragma unroll
    for (int i = 0; i < 2; ++i)
#pragma unroll
        for (int j = 0; j < 4; ++j)
#pragma unroll
            for (int q = 0; q < 4; ++q) acc[i][j][q] = 0.f;

    issue(0); cp_commit();
    issue(1); cp_commit();

    for (int c = 0; c < chunks; ++c) {
        if (c + 2 < chunks) issue(c + 2);
        cp_commit();
        cp_wait2();
        __syncthreads();

        const uint32_t base = sb + (uint32_t)(c % 3) * STAGE_BYTES;
        const uint32_t bAh = base;
        const uint32_t bAl = base + 16384;
        const uint32_t bBh = base + 32768;
        const uint32_t bBl = base + 49152;

#pragma unroll
        for (int ks = 0; ks < 4; ++ks) {
            const uint32_t cA = ((uint32_t)(ks * 32) + selA) ^ xorA;
            const uint32_t cB = ((uint32_t)(ks * 32) + selB) ^ xorB;
            uint32_t ah[2][4], al[2][4];
#pragma unroll
            for (int mf = 0; mf < 2; ++mf) {
                ldm_x4(ah[mf], bAh + rowOffA[mf] + cA);
                ldm_x4(al[mf], bAl + rowOffA[mf] + cA);
            }
            uint32_t bh[4][2], bl[4][2];
#pragma unroll
            for (int nb = 0; nb < 2; ++nb) {
                uint32_t t[4];
                ldm_x4(t, bBh + rowOffB[nb] + cB);
                bh[nb * 2][0] = t[0]; bh[nb * 2][1] = t[1];
                bh[nb * 2 + 1][0] = t[2]; bh[nb * 2 + 1][1] = t[3];
                ldm_x4(t, bBl + rowOffB[nb] + cB);
                bl[nb * 2][0] = t[0]; bl[nb * 2][1] = t[1];
                bl[nb * 2 + 1][0] = t[2]; bl[nb * 2 + 1][1] = t[3];
            }
#pragma unroll
            for (int mf = 0; mf < 2; ++mf)
#pragma unroll
                for (int nf = 0; nf < 4; ++nf) {
                    mma16816(acc[mf][nf], ah[mf], bh[nf]);
                    mma16816(acc[mf][nf], ah[mf], bl[nf]);
                    mma16816(acc[mf][nf], al[mf], bh[nf]);
                }
        }
        __syncthreads();
    }

    const int g = lane >> 2;
    const int t2 = (lane & 3) * 2;
#pragma unroll
    for (int mf = 0; mf < 2; ++mf) {
#pragma unroll
        for (int nf = 0; nf < 4; ++nf) {
            const int col = bn + wn + nf * 8 + t2;
            const int row0 = bm + wm + mf * 16 + g;
            *(float2*)(C + (size_t)row0 * ldc + col) =
                make_float2(acc[mf][nf][0], acc[mf][nf][1]);
            *(float2*)(C + (size_t)(row0 + 8) * ldc + col) =
                make_float2(acc[mf][nf][2], acc[mf][nf][3]);
        }
    }
}

// ---------------- fp32 -> bf16 hi/lo splits ---------------------------------
__global__ __launch_bounds__(256)
void split_kernel(const float* __restrict__ src, __nv_bfloat16* __restrict__ hi,
                  __nv_bfloat16* __restrict__ lo, int n4)
{
    const int i = blockIdx.x * 256 + threadIdx.x;
    if (i >= n4) return;
    const float4 v = ((const float4*)src)[i];
    __nv_bfloat16 h0 = __float2bfloat16(v.x), h1 = __float2bfloat16(v.y);
    __nv_bfloat16 h2 = __float2bfloat16(v.z), h3 = __float2bfloat16(v.w);
    hi[i * 4 + 0] = h0; hi[i * 4 + 1] = h1; hi[i * 4 + 2] = h2; hi[i * 4 + 3] = h3;
    lo[i * 4 + 0] = __float2bfloat16(v.x - __bfloat162float(h0));
    lo[i * 4 + 1] = __float2bfloat16(v.y - __bfloat162float(h1));
    lo[i * 4 + 2] = __float2bfloat16(v.z - __bfloat162float(h2));
    lo[i * 4 + 3] = __float2bfloat16(v.w - __bfloat162float(h3));
}

__global__ __launch_bounds__(256)
void split_pad_kernel(const float* __restrict__ src, __nv_bfloat16* __restrict__ hi,
                      __nv_bfloat16* __restrict__ lo)
{
    const int i = blockIdx.x * 256 + threadIdx.x;
    if (i >= PROJ_PAD * DM / 4) return;
    const int row = i / (DM / 4);
    float4 v = make_float4(0.f, 0.f, 0.f, 0.f);
    if (row < PROJ) v = ((const float4*)src)[i];
    __nv_bfloat16 h0 = __float2bfloat16(v.x), h1 = __float2bfloat16(v.y);
    __nv_bfloat16 h2 = __float2bfloat16(v.z), h3 = __float2bfloat16(v.w);
    hi[i * 4 + 0] = h0; hi[i * 4 + 1] = h1; hi[i * 4 + 2] = h2; hi[i * 4 + 3] = h3;
    lo[i * 4 + 0] = __float2bfloat16(v.x - __bfloat162float(h0));
    lo[i * 4 + 1] = __float2bfloat16(v.y - __bfloat162float(h1));
    lo[i * 4 + 2] = __float2bfloat16(v.z - __bfloat162float(h2));
    lo[i * 4 + 3] = __float2bfloat16(v.w - __bfloat162float(h3));
}

// ---------------- depthwise causal conv (K=4) + bias + SiLU ------------------
__global__ __launch_bounds__(256)
void conv_kernel(const float* __restrict__ conv_w, const float* __restrict__ conv_b)
{
    const int c = blockIdx.x * 256 + threadIdx.x;
    if (c >= CONV_DIM) return;
    const int bl = blockIdx.y;
    const int l = bl & (L_ - 1);
    float acc = conv_b[c];
    const float* w = conv_w + c * 4;
#pragma unroll
    for (int j = 0; j < 4; ++j) {
        const int ll = l - 3 + j;
        if (ll >= 0)
            acc = fmaf(g_proj[(size_t)(bl + j - 3) * PROJ_PAD + INTER + c], w[j], acc);
    }
    g_conv[(size_t)bl * CONV_DIM + c] = siluf(acc);
}

// ---------------- dt = softplus(dt_raw + bias); dA = exp(dt*A) ---------------
__global__ __launch_bounds__(256)
void dt_kernel(const float* __restrict__ dt_bias, const float* __restrict__ A_log)
{
    const int idx = blockIdx.x * 256 + threadIdx.x;
    if (idx >= B_ * L_ * H_) return;
    const int hh = idx & (H_ - 1);
    const int bl = idx >> 5;
    const float x = g_proj[(size_t)bl * PROJ_PAD + INTER + CONV_DIM + hh] + dt_bias[hh];
    const float dt = softplusf(x);
    const float A = -expf(A_log[hh]);
    g_dt[idx] = dt;
    g_dA[idx] = expf(dt * A);
}

// ---------------- chunked scan ----------------------------------------------
// per-chunk decay product Adec[b][c][h] = prod_t dA
__global__ __launch_bounds__(256)
void adec_kernel()
{
    const int i = blockIdx.x * 256 + threadIdx.x;
    if (i >= B_ * NCHUNK * H_) return;
    const int h = i & (H_ - 1);
    const int c = (i >> 5) & (NCHUNK - 1);
    const int b = i >> 10;
    float p = 1.f;
    const float* base = g_dA + ((size_t)(b * L_ + c * TCH)) * H_ + h;
    for (int t = 0; t < TCH; ++t) p *= base[(size_t)t * H_];
    g_adec[i] = p;
}

// Pass 1: per-chunk scan from zero state; store end state.
// Block = (c, h, b). 256 threads: pgrp=tid>>4 (4 p-rows), ngrp=tid&15 (8 n).
__global__ __launch_bounds__(256)
void scan_part1()
{
    const int c = blockIdx.x, h = blockIdx.y, b = blockIdx.z;
    const int tid = threadIdx.x;
    const int pgrp = tid >> 4;
    const int ngrp = tid & 15;
    const int t0 = c * TCH;

    __shared__ float sB[4][128];
    __shared__ float sx[4][64];
    __shared__ float sS[4][2];

    auto issue = [&](int t, int s) {
        const float* base = g_conv + (size_t)(b * L_ + t0 + t) * CONV_DIM;
        if (tid < 32)       cp16(s2u(&sB[s][tid * 4]), base + INTER + tid * 4);
        else if (tid < 48)  cp16(s2u(&sx[s][(tid - 32) * 4]), base + h * P_ + (tid - 32) * 4);
        else if (tid == 48) cp_async4(s2u(&sS[s][0]), g_dA + (size_t)(b * L_ + t0 + t) * H_ + h);
        else if (tid == 49) cp_async4(s2u(&sS[s][1]), g_dt + (size_t)(b * L_ + t0 + t) * H_ + h);
    };

    for (int t = 0; t < 3; ++t) { issue(t, t); cp_commit(); }

    float hst[4][8];
#pragma unroll
    for (int i = 0; i < 4; ++i)
#pragma unroll
        for (int j = 0; j < 8; ++j) hst[i][j] = 0.f;

    for (int t = 0; t < TCH; ++t) {
        cp_wait2();
        __syncthreads();
        if (t + 3 < TCH) issue(t + 3, (t + 3) & 3);
        cp_commit();

        const int s = t & 3;
        const float dA = sS[s][0];
        const float dtv = sS[s][1];
        const float4 xv = *(const float4*)&sx[s][pgrp * 4];
        float bv[8];
        *(float4*)&bv[0] = *(const float4*)&sB[s][ngrp * 8];
        *(float4*)&bv[4] = *(const float4*)&sB[s][ngrp * 8 + 4];
        const float dtx[4] = {dtv * xv.x, dtv * xv.y, dtv * xv.z, dtv * xv.w};
#pragma unroll
        for (int i = 0; i < 4; ++i)
#pragma unroll
            for (int j = 0; j < 8; ++j)
                hst[i][j] = fmaf(dA, hst[i][j], dtx[i] * bv[j]);
    }

    float* st = g_state + (((size_t)(b * NCHUNK + c) * H_ + h)) * (P_ * N_);
#pragma unroll
    for (int i = 0; i < 4; ++i) {
        float* row = st + (pgrp * 4 + i) * N_ + ngrp * 8;
        *(float4*)row = make_float4(hst[i][0], hst[i][1], hst[i][2], hst[i][3]);
        *(float4*)(row + 4) = make_float4(hst[i][4], hst[i][5], hst[i][6], hst[i][7]);
    }
}

// Pass 2: combine chunk states sequentially (parallel over state elements).
__global__ __launch_bounds__(256)
void scan_combine()
{
    const int idx = blockIdx.x * 256 + threadIdx.x;   // B*H*P*N
    if (idx >= B_ * H_ * P_ * N_) return;
    const int h = (idx >> 13) & (H_ - 1);
    const int b = idx >> 18;
    const int pn = idx & (P_ * N_ - 1);
    float carry = 0.f;
#pragma unroll 4
    for (int c = 0; c < NCHUNK; ++c) {
        const size_t off = (((size_t)(b * NCHUNK + c) * H_ + h)) * (P_ * N_) + pn;
        g_init[off] = carry;
        carry = fmaf(g_adec[(b * NCHUNK + c) * H_ + h], carry, g_state[off]);
    }
}

// Pass 3: re-run chunk scan from proper init; emit y.
__global__ __launch_bounds__(256)
void scan_part3()
{
    const int c = blockIdx.x, h = blockIdx.y, b = blockIdx.z;
    const int tid = threadIdx.x;
    const int pgrp = tid >> 4;
    const int ngrp = tid & 15;
    const int t0 = c * TCH;

    __shared__ float sB[4][128];
    __shared__ float sC[4][128];
    __shared__ float sx[4][64];
    __shared__ float sS[4][2];

    auto issue = [&](int t, int s) {
        const float* base = g_conv + (size_t)(b * L_ + t0 + t) * CONV_DIM;
        if (tid < 32)       cp16(s2u(&sB[s][tid * 4]), base + INTER + tid * 4);
        else if (tid < 64)  cp16(s2u(&sC[s][(tid - 32) * 4]), base + INTER + N_ + (tid - 32) * 4);
        else if (tid < 80)  cp16(s2u(&sx[s][(tid - 64) * 4]), base + h * P_ + (tid - 64) * 4);
        else if (tid == 80) cp_async4(s2u(&sS[s][0]), g_dA + (size_t)(b * L_ + t0 + t) * H_ + h);
        else if (tid == 81) cp_async4(s2u(&sS[s][1]), g_dt + (size_t)(b * L_ + t0 + t) * H_ + h);
    };

    for (int t = 0; t < 3; ++t) { issue(t, t); cp_commit(); }

    float hst[4][8];
    {
        const float* st = g_init + (((size_t)(b * NCHUNK + c) * H_ + h)) * (P_ * N_);
#pragma unroll
        for (int i = 0; i < 4; ++i) {
            const float* row = st + (pgrp * 4 + i) * N_ + ngrp * 8;
            const float4 a = *(const float4*)row;
            const float4 d = *(const float4*)(row + 4);
            hst[i][0] = a.x; hst[i][1] = a.y; hst[i][2] = a.z; hst[i][3] = a.w;
            hst[i][4] = d.x; hst[i][5] = d.y; hst[i][6] = d.z; hst[i][7] = d.w;
        }
    }

    for (int t = 0; t < TCH; ++t) {
        cp_wait2();
        __syncthreads();
        if (t + 3 < TCH) issue(t + 3, (t + 3) & 3);
        cp_commit();

        const int s = t & 3;
        const float dA = sS[s][0];
        const float dtv = sS[s][1];
        const float4 xv = *(const float4*)&sx[s][pgrp * 4];
        float bv[8], cv[8];
        *(float4*)&bv[0] = *(const float4*)&sB[s][ngrp * 8];
        *(float4*)&bv[4] = *(const float4*)&sB[s][ngrp * 8 + 4];
        *(float4*)&cv[0] = *(const float4*)&sC[s][ngrp * 8];
        *(float4*)&cv[4] = *(const float4*)&sC[s][ngrp * 8 + 4];
        const float dtx[4] = {dtv * xv.x, dtv * xv.y, dtv * xv.z, dtv * xv.w};
        float y0 = 0.f, y1 = 0.f, y2 = 0.f, y3 = 0.f;
#pragma unroll
        for (int j = 0; j < 8; ++j) {
            hst[0][j] = fmaf(dA, hst[0][j], dtx[0] * bv[j]); y0 = fmaf(hst[0][j], cv[j], y0);
            hst[1][j] = fmaf(dA, hst[1][j], dtx[1] * bv[j]); y1 = fmaf(hst[1][j], cv[j], y1);
            hst[2][j] = fmaf(dA, hst[2][j], dtx[2] * bv[j]); y2 = fmaf(hst[2][j], cv[j], y2);
            hst[3][j] = fmaf(dA, hst[3][j], dtx[3] * bv[j]); y3 = fmaf(hst[3][j], cv[j], y3);
        }
#pragma unroll
        for (int o = 8; o; o >>= 1) {
            y0 += __shfl_xor_sync(0xffffffffu, y0, o);
            y1 += __shfl_xor_sync(0xffffffffu, y1, o);
            y2 += __shfl_xor_sync(0xffffffffu, y2, o);
            y3 += __shfl_xor_sync(0xffffffffu, y3, o);
        }
        if (ngrp == 0) {
            *(float4*)&g_y[(size_t)(b * L_ + t0 + t) * INTER + h * P_ + pgrp * 4] =
                make_float4(y0, y1, y2, y3);
        }
    }
}

// ---------------- y + D*xs, gate*silu, RMSNorm, fused bf16 split -------------
__global__ __launch_bounds__(256)
void gate_rms_kernel(const float* __restrict__ D_param, const float* __restrict__ norm_w)
{
    const int bl = blockIdx.x;
    const int tid = threadIdx.x;
    const float* yrow = g_y + (size_t)bl * INTER;
    const float* grow = g_proj + (size_t)bl * PROJ_PAD;
    const float* xrow = g_conv + (size_t)bl * CONV_DIM;

    float vals[8];
    float ss = 0.f;
#pragma unroll
    for (int r = 0; r < 2; ++r) {
        const int i = tid * 4 + r * 1024;
        const float4 yv = *(const float4*)(yrow + i);
        const float4 gv = *(const float4*)(grow + i);
        const float4 xv = *(const float4*)(xrow + i);
        const float d = D_param[i >> 6];
        float g0 = (yv.x + d * xv.x) * siluf(gv.x);
        float g1 = (yv.y + d * xv.y) * siluf(gv.y);
        float g2 = (yv.z + d * xv.z) * siluf(gv.z);
        float g3 = (yv.w + d * xv.w) * siluf(gv.w);
        vals[r * 4 + 0] = g0; vals[r * 4 + 1] = g1;
        vals[r * 4 + 2] = g2; vals[r * 4 + 3] = g3;
        ss += g0 * g0 + g1 * g1 + g2 * g2 + g3 * g3;
    }

    __shared__ float red[8];
    __shared__ float stot;
#pragma unroll
    for (int o = 16; o; o >>= 1) ss += __shfl_xor_sync(0xffffffffu, ss, o);
    if ((tid & 31) == 0) red[tid >> 5] = ss;
    __syncthreads();
    if (tid == 0) {
        float v = 0.f;
#pragma unroll
        for (int i = 0; i < 8; ++i) v += red[i];
        stot = rsqrtf(v * (1.f / (float)INTER) + EPSV);
    }
    __syncthreads();
    const float rs = stot;

    __nv_bfloat16* yh = g_yh + (size_t)bl * INTER;
    __nv_bfloat16* yl = g_yl + (size_t)bl * INTER;
#pragma unroll
    for (int r = 0; r < 2; ++r) {
        const int i = tid * 4 + r * 1024;
        const float4 nw = *(const float4*)(norm_w + i);
        float o0 = vals[r * 4 + 0] * rs * nw.x;
        float o1 = vals[r * 4 + 1] * rs * nw.y;
        float o2 = vals[r * 4 + 2] * rs * nw.z;
        float o3 = vals[r * 4 + 3] * rs * nw.w;
        __nv_bfloat16 h0 = __float2bfloat16(o0), h1 = __float2bfloat16(o1);
        __nv_bfloat16 h2 = __float2bfloat16(o2), h3 = __float2bfloat16(o3);
        yh[i + 0] = h0; yh[i + 1] = h1; yh[i + 2] = h2; yh[i + 3] = h3;
        yl[i + 0] = __float2bfloat16(o0 - __bfloat162float(h0));
        yl[i + 1] = __float2bfloat16(o1 - __bfloat162float(h1));
        yl[i + 2] = __float2bfloat16(o2 - __bfloat162float(h2));
        yl[i + 3] = __float2bfloat16(o3 - __bfloat162float(h3));
    }
}

// ---------------- launch -----------------------------------------------------
extern "C" void kernel_launch(void* const* d_in, const int* in_sizes, int n_in,
                              void* d_out, int out_size)
{
    const float* hs      = (const float*)d_in[0];
    const float* W_in    = (const float*)d_in[1];
    const float* conv_w  = (const float*)d_in[2];
    const float* conv_b  = (const float*)d_in[3];
    const float* dt_bias = (const float*)d_in[4];
    const float* A_log   = (const float*)d_in[5];
    const float* D_param = (const float*)d_in[6];
    const float* norm_w  = (const float*)d_in[7];
    const float* W_out   = (const float*)d_in[8];
    float* out = (float*)d_out;

    cudaFuncSetAttribute(gemm_mma3, cudaFuncAttributeMaxDynamicSharedMemorySize,
                         GEMM_SMEM_BYTES);

    void *pproj = nullptr;
    void *phh = nullptr, *phl = nullptr, *pwh = nullptr, *pwl = nullptr;
    void *pyh = nullptr, *pyl = nullptr, *poh = nullptr, *pol = nullptr;
    cudaGetSymbolAddress(&pproj, g_proj);
    cudaGetSymbolAddress(&phh, g_hs_hi);
    cudaGetSymbolAddress(&phl, g_hs_lo);
    cudaGetSymbolAddress(&pwh, g_win_hi);
    cudaGetSymbolAddress(&pwl, g_win_lo);
    cudaGetSymbolAddress(&pyh, g_yh);
    cudaGetSymbolAddress(&pyl, g_yl);
    cudaGetSymbolAddress(&poh, g_wo_hi);
    cudaGetSymbolAddress(&pol, g_wo_lo);

    // 0) splits
    {
        const int n4 = B_ * L_ * DM / 4;
        split_kernel<<<(n4 + 255) / 256, 256>>>(hs, (__nv_bfloat16*)phh, (__nv_bfloat16*)phl, n4);
    }
    split_pad_kernel<<<(PROJ_PAD * DM / 4 + 255) / 256, 256>>>(
        W_in, (__nv_bfloat16*)pwh, (__nv_bfloat16*)pwl);
    {
        const int n4 = DM * INTER / 4;
        split_kernel<<<(n4 + 255) / 256, 256>>>(W_out, (__nv_bfloat16*)poh, (__nv_bfloat16*)pol, n4);
    }

    // 1) proj = hs @ W_in^T
    {
        dim3 grid(PROJ_PAD / 128, (B_ * L_) / 128);
        gemm_mma3<<<grid, 512, GEMM_SMEM_BYTES>>>(
            (const __nv_bfloat16*)phh, (const __nv_bfloat16*)phl,
            (const __nv_bfloat16*)pwh, (const __nv_bfloat16*)pwl,
            (float*)pproj, DM, PROJ_PAD);
    }
    // 2) conv + silu
    {
        dim3 grid((CONV_DIM + 255) / 256, B_ * L_);
        conv_kernel<<<grid, 256>>>(conv_w, conv_b);
    }
    // 3) dt / dA
    dt_kernel<<<(B_ * L_ * H_ + 255) / 256, 256>>>(dt_bias, A_log);
    // 4) chunked scan
    adec_kernel<<<(B_ * NCHUNK * H_ + 255) / 256, 256>>>();
    {
        dim3 grid(NCHUNK, H_, B_);
        scan_part1<<<grid, 256>>>();
        scan_combine<<<(B_ * H_ * P_ * N_) / 256, 256>>>();
        scan_part3<<<grid, 256>>>();
    }
    // 5) gate + rmsnorm + split
    gate_rms_kernel<<<B_ * L_, 256>>>(D_param, norm_w);
    // 6) out = g @ W_out^T
    {
        dim3 grid(DM / 128, (B_ * L_) / 128);
        gemm_mma3<<<grid, 512, GEMM_SMEM_BYTES>>>(
            (const __nv_bfloat16*)pyh, (const __nv_bfloat16*)pyl,
            (const __nv_bfloat16*)poh, (const __nv_bfloat16*)pol,
            out, INTER, DM);
    }
}